// round 1
// baseline (speedup 1.0000x reference)
#include <cuda_runtime.h>
#include <cuda_bf16.h>
#include <cstdint>

#define MAXC 64
#define WINF (1<<20)

// ---------------- device globals (scratch; no allocation allowed) ----------------
__device__ float g_act[256u*128u*784u];     // per-neuron activations [n][b][p]
__device__ float g_hidden[128*200];
__device__ int   g_idx[256*MAXC];           // ordered in-lists (edge order)
__device__ int   g_deg[256];
__device__ int   g_wave[256];               // BFS level, WINF if unreachable
__device__ int   g_order[256];              // needed conv neurons grouped by wave
__device__ int   g_wstart[260];
__device__ int   g_W;                       // wave of neuron 255
__device__ unsigned g_barcnt;
__device__ volatile unsigned g_bargen;

// ---------------- scheduler: in-lists + BFS levels + needed-set + wave order ----
__global__ void sched_kernel(const int* __restrict__ src, const int* __restrict__ tgt) {
    __shared__ int s_src[1024], s_tgt[1024];
    __shared__ int s_wave[256];
    __shared__ int s_need[256];
    __shared__ int s_chg;
    int tid = threadIdx.x;

    s_src[tid] = src[tid];
    s_tgt[tid] = tgt[tid];
    if (tid < 256) { s_wave[tid] = WINF; s_need[tid] = 0; }
    if (tid == 0) s_chg = 0;
    __syncthreads();

    // ordered in-lists (edge order == np.where order)
    if (tid < 256) {
        int cnt = 0;
        for (int e = 0; e < 1024; ++e) {
            if (s_tgt[e] == tid) { if (cnt < MAXC) g_idx[tid*MAXC + cnt] = s_src[e]; ++cnt; }
        }
        g_deg[tid] = cnt < MAXC ? cnt : MAXC;
    }
    if (tid == 0) s_wave[0] = 0;
    __syncthreads();

    // parallel Bellman-Ford: BFS levels from node 0
    for (int pass = 0; pass < 300; ++pass) {
        int s = s_src[tid], t = s_tgt[tid];
        int ws = s_wave[s];
        if (ws < WINF && ws + 1 < s_wave[t]) { atomicMin(&s_wave[t], ws + 1); s_chg = 1; }
        __syncthreads();
        int c = s_chg;
        __syncthreads();
        if (tid == 0) s_chg = 0;
        __syncthreads();
        if (!c) break;
    }

    // backward needed-set from node 255 (only inputs with strictly smaller wave count)
    if (tid == 0) s_need[255] = 1;
    __syncthreads();
    for (int pass = 0; pass < 300; ++pass) {
        int s = s_src[tid], t = s_tgt[tid];
        if (s_need[t] && s_wave[s] < s_wave[t] && !s_need[s]) { s_need[s] = 1; s_chg = 1; }
        __syncthreads();
        int c = s_chg;
        __syncthreads();
        if (tid == 0) s_chg = 0;
        __syncthreads();
        if (!c) break;
    }

    if (tid < 256) g_wave[tid] = s_wave[tid];
    if (tid == 0) {
        int W = s_wave[255];
        g_W = W;
        int pos = 0;
        for (int w = 1; w < W; ++w) {
            g_wstart[w] = pos;
            for (int n = 1; n < 255; ++n)
                if (s_need[n] && s_wave[n] == w) g_order[pos++] = n;
        }
        g_wstart[W > 0 ? W : 1] = pos;
    }
}

// ---------------- grid-wide barrier (all blocks co-resident by construction) ----
__device__ __forceinline__ void gsync(int nb) {
    __syncthreads();
    if (threadIdx.x == 0) {
        __threadfence();
        unsigned gen = g_bargen;
        if (atomicAdd(&g_barcnt, 1u) == (unsigned)(nb - 1)) {
            g_barcnt = 0;
            __threadfence();
            g_bargen = gen + 1;
        } else {
            while (g_bargen == gen) { __nanosleep(64); }
            __threadfence();
        }
    }
    __syncthreads();
}

// 7-pixel horizontal register tile: 55 LDS + 175 FMA per channel per thread
__device__ __forceinline__ void conv_accum(const float* __restrict__ im,
                                           const float* __restrict__ wk,
                                           float acc[7]) {
#pragma unroll
    for (int dy = 0; dy < 5; ++dy) {
        const float* rp = im + dy * 33;
        float v[11];
#pragma unroll
        for (int j = 0; j < 11; ++j) v[j] = rp[j];
#pragma unroll
        for (int dx = 0; dx < 5; ++dx) {
            float wv = wk[dy*5 + dx];
#pragma unroll
            for (int o = 0; o < 7; ++o) acc[o] += wv * v[dx + o];
        }
    }
}

// ---------------- main persistent kernel ----------------------------------------
__global__ void __launch_bounds__(224) net_kernel(
    const float* __restrict__ x,
    const float* __restrict__ conv_w, const float* __restrict__ conv_b,
    const float* __restrict__ fc1_w,  const float* __restrict__ fc1_b,
    const float* __restrict__ fc2_w,  const float* __restrict__ fc2_b,
    float* __restrict__ out, int cmax, int fcK, int nb)
{
    __shared__ float img[2*1056];   // two 32x33 padded channel images (halo = zeros)
    __shared__ float wk[25];
    const int tid = threadIdx.x;

    // zero smem once; interiors are rewritten per channel, halo stays zero
    for (int i = tid; i < 2*1056; i += 224) img[i] = 0.f;

    const int bl   = tid / 112;            // which of the 2 batches in this block
    const int tile = tid % 112;            // 112 tiles of 7 px per image
    const int y    = tile >> 2;            // output row 0..27
    const int x0   = (tile & 3) * 7;       // output col base

    // staging offsets: i = tid + k*224 maps to (bb=i/784, p=i%784)
    int ldoff[7];
#pragma unroll
    for (int k = 0; k < 7; ++k) {
        int i  = tid + k * 224;
        int bb = i / 784;
        int p  = i - bb * 784;
        int r  = p / 28;
        ldoff[k] = bb * 1056 + (r + 2) * 33 + (p - r * 28) + 2;
    }
    const float* imbase = img + bl * 1056 + y * 33 + x0;
    const int doff = y * 28 + x0;
    __syncthreads();

    const int W = g_W;

    // ---- wave 0: neuron 0 from x (single channel, conv_w[0,0,0]) ----
    {
        const float bias = conv_b[0];
        for (int t = blockIdx.x; t < 64; t += gridDim.x) {
            const float* sp = x + (size_t)t * 2 * 784;
#pragma unroll
            for (int k = 0; k < 7; ++k) img[ldoff[k]] = sp[tid + k*224];
            if (tid < 25) wk[tid] = conv_w[tid];
            __syncthreads();
            float acc[7];
#pragma unroll
            for (int o = 0; o < 7; ++o) acc[o] = bias;
            conv_accum(imbase, wk, acc);
            float* dst = g_act + (size_t)(t*2 + bl) * 784 + doff;
#pragma unroll
            for (int o = 0; o < 7; ++o) dst[o] = fmaxf(acc[o], 0.f);
            __syncthreads();
        }
    }
    gsync(nb);

    // ---- conv waves 1..W-1 (only needed neurons) ----
    for (int w = 1; w < W; ++w) {
        const int beg = g_wstart[w], end = g_wstart[w+1];
        const int ntasks = (end - beg) * 64;     // (neuron, batch-pair)
        for (int t = blockIdx.x; t < ntasks; t += gridDim.x) {
            const int n  = g_order[beg + (t >> 6)];
            const int pb = t & 63;
            const int wn = g_wave[n];
            const int C  = g_deg[n];
            const float* wbase = conv_w + (size_t)n * cmax * 25;
            float acc[7];
            const float bias = conv_b[n];
#pragma unroll
            for (int o = 0; o < 7; ++o) acc[o] = bias;
            for (int c = 0; c < C; ++c) {
                const int in = g_idx[n*MAXC + c];
                if (g_wave[in] >= wn) continue;  // snapshot semantics: later/equal wave = 0
                const float* sp = g_act + ((size_t)in * 128 + pb * 2) * 784;
#pragma unroll
                for (int k = 0; k < 7; ++k) img[ldoff[k]] = sp[tid + k*224];
                if (tid < 25) wk[tid] = wbase[c*25 + tid];
                __syncthreads();
                conv_accum(imbase, wk, acc);
                __syncthreads();
            }
            float* dst = g_act + ((size_t)n * 128 + pb * 2 + bl) * 784 + doff;
#pragma unroll
            for (int o = 0; o < 7; ++o) dst[o] = fmaxf(acc[o], 0.f);
        }
        gsync(nb);
    }

    // ---- FC1: hidden[b][h] = relu(comp[b] . fc1_w[h] + b), warp computes (h, 4 batches)
    {
        const int lane = tid & 31;
        const int gw   = blockIdx.x * 7 + (tid >> 5);
        const int totw = nb * 7;
        const int fcdeg = g_deg[255];
        for (int o = gw; o < 6400; o += totw) {
            const int h  = o >> 5;
            const int b4 = (o & 31) * 4;
            float a0 = 0.f, a1 = 0.f, a2 = 0.f, a3 = 0.f;
            for (int k = 0; k < fcdeg; ++k) {
                const int in = g_idx[255*MAXC + k];
                if (g_wave[in] >= W) continue;   // not processed before 255's wave -> zeros
                const float* wp = fc1_w + (size_t)h * fcK + k * 784;
                const float* ap = g_act + ((size_t)in * 128 + b4) * 784;
                for (int p = lane; p < 784; p += 32) {
                    float wv = wp[p];
                    a0 += wv * ap[p];
                    a1 += wv * ap[p + 784];
                    a2 += wv * ap[p + 1568];
                    a3 += wv * ap[p + 2352];
                }
            }
#pragma unroll
            for (int off = 16; off; off >>= 1) {
                a0 += __shfl_xor_sync(0xffffffffu, a0, off);
                a1 += __shfl_xor_sync(0xffffffffu, a1, off);
                a2 += __shfl_xor_sync(0xffffffffu, a2, off);
                a3 += __shfl_xor_sync(0xffffffffu, a3, off);
            }
            if (lane == 0) {
                const float bb = fc1_b[h];
                g_hidden[(b4+0)*200 + h] = fmaxf(a0 + bb, 0.f);
                g_hidden[(b4+1)*200 + h] = fmaxf(a1 + bb, 0.f);
                g_hidden[(b4+2)*200 + h] = fmaxf(a2 + bb, 0.f);
                g_hidden[(b4+3)*200 + h] = fmaxf(a3 + bb, 0.f);
            }
        }
    }
    gsync(nb);

    // ---- FC2 + log_softmax: warp per batch row ----
    {
        const int lane = tid & 31;
        const int gw   = blockIdx.x * 7 + (tid >> 5);
        const int totw = nb * 7;
        for (int b = gw; b < 128; b += totw) {
            float acc = 0.f;
            if (lane < 10) {
                acc = fc2_b[lane];
                const float* wp = fc2_w + lane * 200;
                const float* hp = g_hidden + b * 200;
                for (int h2 = 0; h2 < 200; ++h2) acc += hp[h2] * wp[h2];
            }
            float m = (lane < 10) ? acc : -1e30f;
#pragma unroll
            for (int off = 16; off; off >>= 1) m = fmaxf(m, __shfl_xor_sync(0xffffffffu, m, off));
            float e = (lane < 10) ? expf(acc - m) : 0.f;
            float s = e;
#pragma unroll
            for (int off = 16; off; off >>= 1) s += __shfl_xor_sync(0xffffffffu, s, off);
            const float lse = m + logf(s);
            if (lane < 10) out[b*10 + lane] = acc - lse;
        }
    }
}

// ---------------- launch ----------------------------------------------------------
extern "C" void kernel_launch(void* const* d_in, const int* in_sizes, int n_in,
                              void* d_out, int out_size) {
    const float* x      = (const float*)d_in[0];
    const int*   src    = (const int*)  d_in[1];
    const int*   tgt    = (const int*)  d_in[2];
    const float* conv_w = (const float*)d_in[3];
    const float* conv_b = (const float*)d_in[4];
    const float* fc1_w  = (const float*)d_in[5];
    const float* fc1_b  = (const float*)d_in[6];
    const float* fc2_w  = (const float*)d_in[7];
    const float* fc2_b  = (const float*)d_in[8];

    const int cmax = in_sizes[3] / (256 * 25);
    const int fcK  = in_sizes[5] / 200;   // deg_last * 784

    sched_kernel<<<1, 1024>>>(src, tgt);

    int dev = 0, sms = 0, occ = 0;
    cudaGetDevice(&dev);
    cudaDeviceGetAttribute(&sms, cudaDevAttrMultiProcessorCount, dev);
    cudaOccupancyMaxActiveBlocksPerMultiprocessor(&occ, net_kernel, 224, 0);
    int nb = sms * occ;
    if (nb < 1) nb = 1;

    net_kernel<<<nb, 224>>>(x, conv_w, conv_b, fc1_w, fc1_b, fc2_w, fc2_b,
                            (float*)d_out, cmax, fcK, nb);
}

// round 2
// speedup vs baseline: 1.4607x; 1.4607x over previous
#include <cuda_runtime.h>
#include <cuda_bf16.h>
#include <cstdint>

#define NN   256
#define NE   1024
#define MAXC 64
#define WINF (1<<20)

// ---------------- resettable state (one memset per replay) ----------------
struct Flags {
    int done[NN * 64];   // (neuron, batch-pair) completion flags
    int sched_ready;
};
__device__ Flags g_flags;

// ---------------- persistent scratch (rewritten every replay before use) ----
__device__ float g_act[(size_t)NN * 128 * 784];   // [n][b][p]
__device__ float g_hidden[128 * 200];
__device__ int   g_fin[NN * MAXC];    // filtered input neuron ids
__device__ int   g_fcc[NN * MAXC];    // original channel rank (weight offset)
__device__ int   g_fdeg[NN];          // filtered in-degree
__device__ int   g_order[NN];         // needed conv neurons, wave-major
__device__ int   g_ntasks;            // (#needed conv neurons) * 64

// 7-pixel horizontal register tile: 55 LDS + 175 FMA per channel per thread
__device__ __forceinline__ void conv_accum(const float* __restrict__ im,
                                           const float* __restrict__ wk,
                                           float acc[7]) {
#pragma unroll
    for (int dy = 0; dy < 5; ++dy) {
        const float* rp = im + dy * 33;
        float v[11];
#pragma unroll
        for (int j = 0; j < 11; ++j) v[j] = rp[j];
#pragma unroll
        for (int dx = 0; dx < 5; ++dx) {
            float wv = wk[dy * 5 + dx];
#pragma unroll
            for (int o = 0; o < 7; ++o) acc[o] += wv * v[dx + o];
        }
    }
}

// =====================================================================
// K1: fused scheduler (block 0) + wave0 + dataflow conv execution
// =====================================================================
__global__ void __launch_bounds__(224) net_kernel(
    const float* __restrict__ x,
    const int* __restrict__ src, const int* __restrict__ tgt,
    const float* __restrict__ conv_w, const float* __restrict__ conv_b,
    int cmax, int nb)
{
    __shared__ float img[2 * 1056];     // two 32x33 padded images (halo stays 0)
    __shared__ float wk[32];
    // scheduler shared (block 0 only)
    __shared__ int s_src[NE], s_tgt[NE];
    __shared__ int s_wave[NN], s_need[NN], s_list[NN];
    __shared__ int s_chg, s_cnt;

    const int tid = threadIdx.x;
    const int bid = blockIdx.x;

    for (int i = tid; i < 2 * 1056; i += 224) img[i] = 0.f;

    const int bl   = tid / 112;
    const int tile = tid % 112;
    const int y    = tile >> 2;
    const int x0   = (tile & 3) * 7;
    int ldoff[7];
#pragma unroll
    for (int k = 0; k < 7; ++k) {
        int i  = tid + k * 224;
        int bb = i / 784;
        int p  = i - bb * 784;
        int r  = p / 28;
        ldoff[k] = bb * 1056 + (r + 2) * 33 + (p - r * 28) + 2;
    }
    const float* imbase = img + bl * 1056 + y * 33 + x0;
    const int    doff   = y * 28 + x0;
    __syncthreads();

    // ---------------- block 0: schedule ----------------
    if (bid == 0) {
        for (int i = tid; i < NE; i += 224) { s_src[i] = src[i]; s_tgt[i] = tgt[i]; }
        for (int i = tid; i < NN; i += 224) { s_wave[i] = (i == 0) ? 0 : WINF; s_need[i] = 0; }
        if (tid == 0) { s_chg = 0; s_cnt = 0; }
        __syncthreads();

        // edge-parallel BFS levels from neuron 0
        for (int pass = 0; pass < 300; ++pass) {
            for (int e = tid; e < NE; e += 224) {
                int ws = s_wave[s_src[e]];
                if (ws + 1 < s_wave[s_tgt[e]]) { atomicMin(&s_wave[s_tgt[e]], ws + 1); s_chg = 1; }
            }
            __syncthreads();
            int c = s_chg; __syncthreads();
            if (tid == 0) s_chg = 0;
            __syncthreads();
            if (!c) break;
        }
        const int W = s_wave[255];

        // backward needed-set from 255 via strictly-decreasing-wave edges
        if (tid == 0) s_need[255] = 1;
        __syncthreads();
        for (int pass = 0; pass < 300; ++pass) {
            for (int e = tid; e < NE; e += 224) {
                int s = s_src[e], t = s_tgt[e];
                if (s_need[t] && s_wave[s] < s_wave[t] && !s_need[s]) { s_need[s] = 1; s_chg = 1; }
            }
            __syncthreads();
            int c = s_chg; __syncthreads();
            if (tid == 0) s_chg = 0;
            __syncthreads();
            if (!c) break;
        }

        // wave-major ordered list of needed conv neurons (deterministic ranks)
        for (int n = tid; n < NN; n += 224) {
            if (n != 0 && n != 255 && s_need[n]) {
                int r = 0;
                for (int m = 1; m < NN - 1; ++m)
                    if (s_need[m] && (s_wave[m] < s_wave[n] ||
                                      (s_wave[m] == s_wave[n] && m < n))) r++;
                s_list[r] = n;
                atomicAdd(&s_cnt, 1);
            }
        }
        __syncthreads();
        const int total = s_cnt;

        // filtered in-lists via warp ballots (needed neurons + 255)
        {
            const int wid = tid >> 5, lane = tid & 31;
            for (int ni = wid; ni <= total; ni += 7) {
                int n  = (ni == total) ? 255 : s_list[ni];
                int wn = s_wave[n];
                int cbase = 0, cnt = 0;
                for (int ch = 0; ch < NE; ch += 32) {
                    int e = ch + lane;
                    int te = s_tgt[e], se = s_src[e];
                    unsigned m_all  = __ballot_sync(0xffffffffu, te == n);
                    unsigned m_keep = __ballot_sync(0xffffffffu, te == n && s_wave[se] < wn);
                    if (m_keep & (1u << lane)) {
                        int c   = cbase + __popc(m_all  & ((1u << lane) - 1));
                        int pos = cnt   + __popc(m_keep & ((1u << lane) - 1));
                        if (pos < MAXC) { g_fin[n * MAXC + pos] = se; g_fcc[n * MAXC + pos] = c; }
                    }
                    cbase += __popc(m_all);
                    cnt   += __popc(m_keep);
                }
                if (lane == 0) g_fdeg[n] = cnt < MAXC ? cnt : MAXC;
            }
        }
        for (int i = tid; i < total; i += 224) g_order[i] = s_list[i];
        if (tid == 0) g_ntasks = total * 64;
        __threadfence();
        __syncthreads();
        if (tid == 0) *(volatile int*)&g_flags.sched_ready = 1;
    }

    // ---------------- wave 0: neuron 0 from x ----------------
    {
        const float bias = conv_b[0];
        for (int t = bid; t < 64; t += nb) {
            const float* sp = x + (size_t)t * 1568;
#pragma unroll
            for (int k = 0; k < 7; ++k) img[ldoff[k]] = sp[tid + k * 224];
            if (tid < 25) wk[tid] = conv_w[tid];
            __syncthreads();
            float acc[7];
#pragma unroll
            for (int o = 0; o < 7; ++o) acc[o] = bias;
            conv_accum(imbase, wk, acc);
            float* dst = g_act + (size_t)(t * 2 + bl) * 784 + doff;
#pragma unroll
            for (int o = 0; o < 7; ++o) dst[o] = fmaxf(acc[o], 0.f);
            __threadfence();
            __syncthreads();
            if (tid == 0) *(volatile int*)&g_flags.done[t] = 1;
        }
    }

    // ---------------- wait for schedule ----------------
    if (bid != 0) {
        if (tid == 0) {
            volatile int* f = &g_flags.sched_ready;
            while (!*f) __nanosleep(128);
        }
        __syncthreads();
        __threadfence();
    }

    // ---------------- dataflow conv tasks (waves >= 1) ----------------
    const int ntasks = g_ntasks;
    for (int t = bid; t < ntasks; t += nb) {
        const int ni = t >> 6;
        const int pb = t & 63;
        const int n  = g_order[ni];
        const int C  = g_fdeg[n];

        // spin until all filtered inputs for this batch-pair are done
        for (int k = tid; k < C; k += 224) {
            volatile int* f = &g_flags.done[g_fin[n * MAXC + k] * 64 + pb];
            while (!*f) __nanosleep(64);
        }
        __syncthreads();
        __threadfence();

        float acc[7];
        const float bias = conv_b[n];
#pragma unroll
        for (int o = 0; o < 7; ++o) acc[o] = bias;

        const float* wbase = conv_w + (size_t)n * cmax * 25;
        for (int c = 0; c < C; ++c) {
            const int in = g_fin[n * MAXC + c];
            const float* sp = g_act + ((size_t)in * 128 + pb * 2) * 784;
#pragma unroll
            for (int k = 0; k < 7; ++k) img[ldoff[k]] = sp[tid + k * 224];
            if (tid < 25) wk[tid] = wbase[g_fcc[n * MAXC + c] * 25 + tid];
            __syncthreads();
            conv_accum(imbase, wk, acc);
            __syncthreads();
        }
        float* dst = g_act + ((size_t)n * 128 + pb * 2 + bl) * 784 + doff;
#pragma unroll
        for (int o = 0; o < 7; ++o) dst[o] = fmaxf(acc[o], 0.f);
        __threadfence();
        __syncthreads();
        if (tid == 0) *(volatile int*)&g_flags.done[n * 64 + pb] = 1;
    }
}

// =====================================================================
// K2: FC1 — warp computes an 8h x 8b tile (64 accumulators)
// =====================================================================
__global__ void __launch_bounds__(256) fc1_kernel(
    const float* __restrict__ fc1_w, const float* __restrict__ fc1_b, int fcK)
{
    const int wid  = threadIdx.x >> 5;
    const int lane = threadIdx.x & 31;
    const int o    = blockIdx.x * 8 + wid;     // 0..399
    const int h0   = (o / 16) * 8;
    const int b0   = (o % 16) * 8;

    const int fdeg = g_fdeg[255];
    float acc[8][8];
#pragma unroll
    for (int j = 0; j < 8; ++j)
#pragma unroll
        for (int i = 0; i < 8; ++i) acc[j][i] = 0.f;

    for (int k = 0; k < fdeg; ++k) {
        const int in = g_fin[255 * MAXC + k];
        const int c  = g_fcc[255 * MAXC + k];
        const float* wp = fc1_w + (size_t)c * 784 + (size_t)h0 * fcK;
        const float* ap = g_act + ((size_t)in * 128 + b0) * 784;
        for (int p = lane; p < 784; p += 32) {
            float wv[8], av[8];
#pragma unroll
            for (int j = 0; j < 8; ++j) wv[j] = wp[(size_t)j * fcK + p];
#pragma unroll
            for (int i = 0; i < 8; ++i) av[i] = ap[p + i * 784];
#pragma unroll
            for (int j = 0; j < 8; ++j)
#pragma unroll
                for (int i = 0; i < 8; ++i) acc[j][i] += wv[j] * av[i];
        }
    }

#pragma unroll
    for (int j = 0; j < 8; ++j) {
        const float bb = (lane == 0) ? fc1_b[h0 + j] : 0.f;
#pragma unroll
        for (int i = 0; i < 8; ++i) {
            float v = acc[j][i];
#pragma unroll
            for (int off = 16; off; off >>= 1) v += __shfl_xor_sync(0xffffffffu, v, off);
            if (lane == 0)
                g_hidden[(b0 + i) * 200 + h0 + j] = fmaxf(v + bb, 0.f);
        }
    }
}

// =====================================================================
// K3: FC2 + log_softmax — one warp per batch row
// =====================================================================
__global__ void __launch_bounds__(256) fc2_kernel(
    const float* __restrict__ fc2_w, const float* __restrict__ fc2_b,
    float* __restrict__ out)
{
    const int wid  = threadIdx.x >> 5;
    const int lane = threadIdx.x & 31;
    const int b    = blockIdx.x * 8 + wid;    // 0..127

    float acc = 0.f;
    if (lane < 10) {
        acc = fc2_b[lane];
        const float* wp = fc2_w + lane * 200;
        const float* hp = g_hidden + b * 200;
        for (int h = 0; h < 200; ++h) acc += hp[h] * wp[h];
    }
    float m = (lane < 10) ? acc : -1e30f;
#pragma unroll
    for (int off = 16; off; off >>= 1) m = fmaxf(m, __shfl_xor_sync(0xffffffffu, m, off));
    float e = (lane < 10) ? expf(acc - m) : 0.f;
    float s = e;
#pragma unroll
    for (int off = 16; off; off >>= 1) s += __shfl_xor_sync(0xffffffffu, s, off);
    const float lse = m + logf(s);
    if (lane < 10) out[b * 10 + lane] = acc - lse;
}

// ---------------- launch ----------------
extern "C" void kernel_launch(void* const* d_in, const int* in_sizes, int n_in,
                              void* d_out, int out_size) {
    const float* x      = (const float*)d_in[0];
    const int*   src    = (const int*)  d_in[1];
    const int*   tgt    = (const int*)  d_in[2];
    const float* conv_w = (const float*)d_in[3];
    const float* conv_b = (const float*)d_in[4];
    const float* fc1_w  = (const float*)d_in[5];
    const float* fc1_b  = (const float*)d_in[6];
    const float* fc2_w  = (const float*)d_in[7];
    const float* fc2_b  = (const float*)d_in[8];

    const int cmax = in_sizes[3] / (NN * 25);
    const int fcK  = in_sizes[5] / 200;

    void* flagsPtr = nullptr;
    cudaGetSymbolAddress(&flagsPtr, g_flags);
    cudaMemsetAsync(flagsPtr, 0, sizeof(Flags), 0);

    int dev = 0, sms = 0, occ = 0;
    cudaGetDevice(&dev);
    cudaDeviceGetAttribute(&sms, cudaDevAttrMultiProcessorCount, dev);
    cudaOccupancyMaxActiveBlocksPerMultiprocessor(&occ, net_kernel, 224, 0);
    int nb = sms * occ;
    if (nb < 2) nb = 2;

    net_kernel<<<nb, 224>>>(x, src, tgt, conv_w, conv_b, cmax, nb);
    fc1_kernel<<<50, 256>>>(fc1_w, fc1_b, fcK);
    fc2_kernel<<<16, 256>>>(fc2_w, fc2_b, (float*)d_out);
}